// round 7
// baseline (speedup 1.0000x reference)
#include <cuda_runtime.h>
#include <cuda_bf16.h>
#include <math.h>
#include <stdint.h>

// Problem constants
#define BATCH 512
#define DD    128
#define KQ    131072
#define RR    1024           // 2 views * BATCH rows
#define NCOL  256            // queue cols per CTA
#define NTIL  (KQ / NCOL)    // 512 col tiles
#define NRM   (RR / 128)     // 8 row tiles per CTA loop
#define KS    136            // smem row stride in bf16 units (272B, conflict-free)

// -------------------- device scratch --------------------
__device__ float              g_zn[RR * DD];
__device__ float              g_pn[RR * DD];
__device__ __nv_bfloat16      g_ah[RR * DD];     // bf16 hi of normalized z
__device__ __nv_bfloat16      g_al[RR * DD];     // bf16 lo
__device__ float              g_inv[KQ];
__device__ unsigned long long g_part[(size_t)RR * NTIL];
__device__ int                g_idx[RR];
__device__ float              g_loss[RR];

__device__ __forceinline__ unsigned fkey(float f) {
    unsigned u = __float_as_uint(f);
    unsigned m = (unsigned)(((int)u) >> 31);
    return u ^ (m | 0x80000000u);
}
__device__ __forceinline__ uint16_t bfbits(float v) {
    __nv_bfloat16 h = __float2bfloat16(v);
    return *(uint16_t*)&h;
}
__device__ __forceinline__ float bffloat(uint16_t b) {
    __nv_bfloat16 h = *(__nv_bfloat16*)&b;
    return __bfloat162float(h);
}

#define MMA_BF16(cr, a, b0, b1)                                                   \
    asm volatile("mma.sync.aligned.m16n8k16.row.col.f32.bf16.bf16.f32 "           \
        "{%0,%1,%2,%3}, {%4,%5,%6,%7}, {%8,%9}, {%0,%1,%2,%3};"                   \
        : "+f"((cr)[0]), "+f"((cr)[1]), "+f"((cr)[2]), "+f"((cr)[3])              \
        : "r"((a)[0]), "r"((a)[1]), "r"((a)[2]), "r"((a)[3]), "r"(b0), "r"(b1))

// -------------------- 1. normalize rows + bf16 split of z --------------------
__global__ void k_norm_rows(const float* __restrict__ p0, const float* __restrict__ p1,
                            const float* __restrict__ z0, const float* __restrict__ z1) {
    int r = blockIdx.x, t = threadIdx.x;
    const float* srcP = (r < BATCH ? p0 : p1) + (size_t)(r & (BATCH - 1)) * DD;
    const float* srcZ = (r < BATCH ? z0 : z1) + (size_t)(r & (BATCH - 1)) * DD;
    float vp = srcP[t], vz = srcZ[t];
    float sp = vp * vp, sz = vz * vz;
    #pragma unroll
    for (int o = 16; o; o >>= 1) {
        sp += __shfl_xor_sync(0xFFFFFFFFu, sp, o);
        sz += __shfl_xor_sync(0xFFFFFFFFu, sz, o);
    }
    __shared__ float wsP[4], wsZ[4];
    if ((t & 31) == 0) { wsP[t >> 5] = sp; wsZ[t >> 5] = sz; }
    __syncthreads();
    sp = wsP[0] + wsP[1] + wsP[2] + wsP[3];
    sz = wsZ[0] + wsZ[1] + wsZ[2] + wsZ[3];
    float zp = vp * (1.0f / sqrtf(sp));
    float zz = vz * (1.0f / sqrtf(sz));
    size_t o = (size_t)r * DD + t;
    g_pn[o] = zp;
    g_zn[o] = zz;
    __nv_bfloat16 h = __float2bfloat16(zz);
    g_ah[o] = h;
    g_al[o] = __float2bfloat16(zz - __bfloat162float(h));
}

// -------------------- 2. queue column inverse norms --------------------
__global__ void k_colnorm(const float* __restrict__ q) {
    int k = blockIdx.x * blockDim.x + threadIdx.x;
    const float* p = q + k;
    float s = 0.f;
    #pragma unroll 8
    for (int d = 0; d < DD; d++) {
        float v = p[(size_t)d * KQ];
        s = fmaf(v, v, s);
    }
    g_inv[k] = 1.0f / sqrtf(s);
}

// -------------------- 3. mma.sync split-bf16 GEMM + masked argmax --------------------
// dyn smem: AH[128][KS] AL[128][KS] BH[256][KS] BL[256][KS]  (bf16) = 208,896 B
#define SM_AH 0
#define SM_AL (128 * KS)
#define SM_BH (256 * KS)
#define SM_BL (512 * KS)
#define SM_DYN (768 * KS * 2)

__global__ void __launch_bounds__(256, 1) k_mma(const float* __restrict__ Q,
                                                const int* __restrict__ qid,
                                                const int* __restrict__ ids) {
    extern __shared__ uint16_t sm[];
    uint16_t* AH = sm + SM_AH;
    uint16_t* AL = sm + SM_AL;
    uint16_t* BH = sm + SM_BH;
    uint16_t* BL = sm + SM_BL;
    __shared__ float invs[NCOL];
    __shared__ int   qids[NCOL];
    __shared__ int   sIds[BATCH];
    __shared__ unsigned long long red[128][2];

    int t = threadIdx.x, lane = t & 31;
    int g = lane >> 2, q = lane & 3;
    int wid = t >> 5, wm = wid & 3, wn = wid >> 2;
    int bx = blockIdx.x, cn = bx * NCOL;

    invs[t] = g_inv[cn + t];
    qids[t] = qid[cn + t];
    sIds[t]       = ids[t];
    sIds[t + 256] = ids[t + 256];

    // ---- B tile: queue[0..127][cn..cn+255] fp32 -> bf16 hi/lo, layout [col][d] ----
    {
        int colc = (t & 63) * 4;
        int d0 = t >> 6;
        #pragma unroll 4
        for (int i = 0; i < 32; i++) {
            int d = d0 + i * 4;
            float4 v = *(const float4*)(Q + (size_t)d * KQ + cn + colc);
            float vv[4] = {v.x, v.y, v.z, v.w};
            #pragma unroll
            for (int j = 0; j < 4; j++) {
                uint16_t hb = bfbits(vv[j]);
                uint16_t lb = bfbits(vv[j] - bffloat(hb));
                BH[(colc + j) * KS + d] = hb;
                BL[(colc + j) * KS + d] = lb;
            }
        }
    }

    for (int rm = 0; rm < NRM; rm++) {
        __syncthreads();   // prev iteration's reads of A / red done; safe to overwrite
        // ---- A tile: rows rm*128..+127, [row][d] bf16 hi/lo ----
        {
            int row = t >> 1, half = t & 1;
            const uint4* sh = (const uint4*)(g_ah + (size_t)(rm * 128 + row) * DD + half * 64);
            const uint4* sl = (const uint4*)(g_al + (size_t)(rm * 128 + row) * DD + half * 64);
            uint4* dh = (uint4*)(AH + row * KS + half * 64);
            uint4* dl = (uint4*)(AL + row * KS + half * 64);
            #pragma unroll
            for (int i = 0; i < 8; i++) { dh[i] = sh[i]; dl[i] = sl[i]; }
        }
        __syncthreads();

        float c[2][16][4];
        #pragma unroll
        for (int mi = 0; mi < 2; mi++)
            #pragma unroll
            for (int nj = 0; nj < 16; nj++)
                #pragma unroll
                for (int cc = 0; cc < 4; cc++) c[mi][nj][cc] = 0.0f;

        const uint16_t* apH = AH + (wm * 32 + g) * KS + 2 * q;
        const uint16_t* apL = AL + (wm * 32 + g) * KS + 2 * q;
        const uint16_t* bpH = BH + (wn * 128 + g) * KS + 2 * q;
        const uint16_t* bpL = BL + (wn * 128 + g) * KS + 2 * q;

        #pragma unroll 1
        for (int ks = 0; ks < 8; ks++) {
            int ko = ks * 16;
            uint32_t ah[2][4], al[2][4];
            #pragma unroll
            for (int mi = 0; mi < 2; mi++) {
                const uint16_t* p = apH + mi * 16 * KS + ko;
                ah[mi][0] = *(const uint32_t*)p;
                ah[mi][1] = *(const uint32_t*)(p + 8 * KS);
                ah[mi][2] = *(const uint32_t*)(p + 8);
                ah[mi][3] = *(const uint32_t*)(p + 8 * KS + 8);
                const uint16_t* pl = apL + mi * 16 * KS + ko;
                al[mi][0] = *(const uint32_t*)pl;
                al[mi][1] = *(const uint32_t*)(pl + 8 * KS);
                al[mi][2] = *(const uint32_t*)(pl + 8);
                al[mi][3] = *(const uint32_t*)(pl + 8 * KS + 8);
            }
            // pass 1: Ah * Bh
            #pragma unroll
            for (int nj = 0; nj < 16; nj++) {
                const uint16_t* pb = bpH + nj * 8 * KS + ko;
                uint32_t b0 = *(const uint32_t*)pb, b1 = *(const uint32_t*)(pb + 8);
                MMA_BF16(c[0][nj], ah[0], b0, b1);
                MMA_BF16(c[1][nj], ah[1], b0, b1);
            }
            // pass 2: Ah * Bl
            #pragma unroll
            for (int nj = 0; nj < 16; nj++) {
                const uint16_t* pb = bpL + nj * 8 * KS + ko;
                uint32_t b0 = *(const uint32_t*)pb, b1 = *(const uint32_t*)(pb + 8);
                MMA_BF16(c[0][nj], ah[0], b0, b1);
                MMA_BF16(c[1][nj], ah[1], b0, b1);
            }
            // pass 3: Al * Bh
            #pragma unroll
            for (int nj = 0; nj < 16; nj++) {
                const uint16_t* pb = bpH + nj * 8 * KS + ko;
                uint32_t b0 = *(const uint32_t*)pb, b1 = *(const uint32_t*)(pb + 8);
                MMA_BF16(c[0][nj], al[0], b0, b1);
                MMA_BF16(c[1][nj], al[1], b0, b1);
            }
        }

        // ---- epilogue: scale, mask, per-row argmax ----
        #pragma unroll
        for (int mi = 0; mi < 2; mi++) {
            #pragma unroll
            for (int rh = 0; rh < 2; rh++) {
                int lrow = wm * 32 + mi * 16 + rh * 8 + g;
                int id_i = sIds[(rm * 128 + lrow) & (BATCH - 1)];
                unsigned long long best = 0ull;
                #pragma unroll
                for (int nj = 0; nj < 16; nj++) {
                    #pragma unroll
                    for (int cc = 0; cc < 2; cc++) {
                        int col = wn * 128 + nj * 8 + 2 * q + cc;
                        float v = c[mi][nj][rh * 2 + cc] * invs[col];
                        if (qids[col] == id_i) v = -1.0f;
                        unsigned long long key =
                            ((unsigned long long)fkey(v) << 32) | (unsigned)(~(cn + col));
                        if (key > best) best = key;
                    }
                }
                unsigned long long o1 = __shfl_xor_sync(0xFFFFFFFFu, best, 1);
                if (o1 > best) best = o1;
                unsigned long long o2 = __shfl_xor_sync(0xFFFFFFFFu, best, 2);
                if (o2 > best) best = o2;
                if (q == 0) red[lrow][wn] = best;
            }
        }
        __syncthreads();
        if (t < 128) {
            unsigned long long b = red[t][0];
            if (red[t][1] > b) b = red[t][1];
            g_part[(size_t)(rm * 128 + t) * NTIL + bx] = b;
        }
    }
}

// -------------------- 4. reduce per-tile argmax partials --------------------
__global__ void k_argreduce() {
    int r = blockIdx.x, t = threadIdx.x;  // 256 threads, NTIL=512
    const unsigned long long* p = &g_part[(size_t)r * NTIL];
    unsigned long long b = p[t];
    unsigned long long v = p[t + 256];
    if (v > b) b = v;
    __shared__ unsigned long long s[256];
    s[t] = b;
    __syncthreads();
    for (int o = 128; o; o >>= 1) {
        if (t < o) { if (s[t + o] > s[t]) s[t] = s[t + o]; }
        __syncthreads();
    }
    if (t == 0) g_idx[r] = (int)(~(unsigned)s[0]);
}

// -------------------- 5. contrastive loss diag terms --------------------
__global__ void k_loss(const float* __restrict__ Q) {
    int b = blockIdx.x;
    int view = b >> 9;
    int i = b & (BATCH - 1);
    int t = threadIdx.x;  // 128

    int nidx = (view == 0) ? g_idx[BATCH + i] : g_idx[i];
    __shared__ float nn[128];
    nn[t] = Q[(size_t)t * KQ + nidx] * g_inv[nidx];
    __syncthreads();

    const float* p = g_pn + (size_t)view * BATCH * DD;
    float lg[4];
    float mx = -1e30f;
    #pragma unroll
    for (int jj = 0; jj < 4; jj++) {
        int j = t + jj * 128;
        const float4* pj = (const float4*)&p[(size_t)j * DD];
        float s = 0.f;
        #pragma unroll
        for (int d4 = 0; d4 < 32; d4++) {
            float4 pv = pj[d4];
            s = fmaf(nn[d4 * 4 + 0], pv.x, s);
            s = fmaf(nn[d4 * 4 + 1], pv.y, s);
            s = fmaf(nn[d4 * 4 + 2], pv.z, s);
            s = fmaf(nn[d4 * 4 + 3], pv.w, s);
        }
        lg[jj] = s * (1.0f / 0.07f);
        mx = fmaxf(mx, lg[jj]);
    }

    __shared__ float sm[128];
    __shared__ float sdiag;
    #pragma unroll
    for (int jj = 0; jj < 4; jj++)
        if (t + jj * 128 == i) sdiag = lg[jj];

    sm[t] = mx;
    for (int o = 64; o; o >>= 1) {
        __syncthreads();
        if (t < o) sm[t] = fmaxf(sm[t], sm[t + o]);
    }
    __syncthreads();
    float m = sm[0];
    __syncthreads();

    float se = 0.f;
    #pragma unroll
    for (int jj = 0; jj < 4; jj++) se += expf(lg[jj] - m);
    sm[t] = se;
    for (int o = 64; o; o >>= 1) {
        __syncthreads();
        if (t < o) sm[t] += sm[t + o];
    }
    __syncthreads();
    if (t == 0) g_loss[b] = -(sdiag - m - logf(sm[0]));
}

// -------------------- 6. final loss reduce --------------------
__global__ void k_lossred(float* __restrict__ out) {
    int t = threadIdx.x;  // 1024
    __shared__ float s[1024];
    s[t] = g_loss[t];
    __syncthreads();
    for (int o = 512; o; o >>= 1) {
        if (t < o) s[t] += s[t + o];
        __syncthreads();
    }
    if (t == 0) out[0] = s[0] * (1.0f / 1024.0f);
}

// -------------------- 7. write new_queue --------------------
__global__ void k_writeq(const float* __restrict__ Q, float* __restrict__ out) {
    size_t e = (size_t)blockIdx.x * blockDim.x + threadIdx.x;
    int k4 = (int)(e % (KQ / 4));
    int d  = (int)(e / (KQ / 4));
    int k  = k4 * 4;
    float x, y, z, w;
    if (k >= BATCH) {
        float4 qv = *(const float4*)&Q[(size_t)d * KQ + k];
        float4 iv = *(const float4*)&g_inv[k];
        x = qv.x * iv.x; y = qv.y * iv.y; z = qv.z * iv.z; w = qv.w * iv.w;
    } else {
        x = g_zn[(size_t)(k + 0) * DD + d];
        y = g_zn[(size_t)(k + 1) * DD + d];
        z = g_zn[(size_t)(k + 2) * DD + d];
        w = g_zn[(size_t)(k + 3) * DD + d];
    }
    size_t o = (size_t)d * KQ + k;   // out base is d_out+1 (4B aligned) -> scalar stores
    out[o] = x; out[o + 1] = y; out[o + 2] = z; out[o + 3] = w;
}

// -------------------- 8. write new_queue_id + new_ptr --------------------
__global__ void k_writeids(const int* __restrict__ qid, const int* __restrict__ ids,
                           float* __restrict__ out) {
    int k = blockIdx.x * blockDim.x + threadIdx.x;
    if (k < KQ) out[k] = (float)(k < BATCH ? ids[k] : qid[k]);
    if (k == 0) out[KQ] = (float)BATCH;  // (0 + 512) % 131072
}

// -------------------- launch --------------------
extern "C" void kernel_launch(void* const* d_in, const int* in_sizes, int n_in,
                              void* d_out, int out_size) {
    const float* predict0 = (const float*)d_in[0];
    const float* predict1 = (const float*)d_in[1];
    const float* project0 = (const float*)d_in[2];
    const float* project1 = (const float*)d_in[3];
    const float* queue    = (const float*)d_in[4];
    const int*   queue_id = (const int*)d_in[5];
    const int*   ids      = (const int*)d_in[6];
    float* out = (float*)d_out;

    cudaFuncSetAttribute(k_mma, cudaFuncAttributeMaxDynamicSharedMemorySize, SM_DYN);

    k_norm_rows<<<RR, 128>>>(predict0, predict1, project0, project1);
    k_colnorm<<<KQ / 256, 256>>>(queue);
    k_mma<<<NTIL, 256, SM_DYN>>>(queue, queue_id, ids);
    k_argreduce<<<RR, 256>>>();
    k_loss<<<RR, 128>>>(queue);
    k_lossred<<<1, 1024>>>(out);
    k_writeq<<<((size_t)DD * KQ / 4) / 256, 256>>>(queue, out + 1);
    k_writeids<<<KQ / 256, 256>>>(queue_id, ids, out + 1 + (size_t)DD * KQ);
}

// round 9
// speedup vs baseline: 1.0044x; 1.0044x over previous
#include <cuda_runtime.h>
#include <cuda_bf16.h>
#include <math.h>
#include <stdint.h>

// Problem constants
#define BATCH 512
#define DD    128
#define KQ    131072
#define RR    1024           // 2 views * BATCH rows
#define NCOL  256            // queue cols per CTA
#define NTIL  (KQ / NCOL)    // 512 col tiles
#define NRM   (RR / 128)     // 8 row tiles per CTA loop
#define KS    136            // smem row stride in bf16 units (272B, conflict-free)

// -------------------- device scratch --------------------
__device__ float              g_zn[RR * DD];
__device__ float              g_pn[RR * DD];
__device__ __nv_bfloat16      g_ah[RR * DD];     // bf16 hi of normalized z
__device__ __nv_bfloat16      g_al[RR * DD];     // bf16 lo
__device__ float              g_inv[KQ];
__device__ unsigned long long g_part[(size_t)RR * NTIL];
__device__ int                g_idx[RR];
__device__ float              g_loss[RR];

__device__ __forceinline__ unsigned fkey(float f) {
    unsigned u = __float_as_uint(f);
    unsigned m = (unsigned)(((int)u) >> 31);
    return u ^ (m | 0x80000000u);
}
__device__ __forceinline__ uint16_t bfbits(float v) {
    __nv_bfloat16 h = __float2bfloat16(v);
    return *(uint16_t*)&h;
}
__device__ __forceinline__ float bffloat(uint16_t b) {
    __nv_bfloat16 h = *(__nv_bfloat16*)&b;
    return __bfloat162float(h);
}

#define MMA_BF16(cr, a, b0, b1)                                                   \
    asm volatile("mma.sync.aligned.m16n8k16.row.col.f32.bf16.bf16.f32 "           \
        "{%0,%1,%2,%3}, {%4,%5,%6,%7}, {%8,%9}, {%0,%1,%2,%3};"                   \
        : "+f"((cr)[0]), "+f"((cr)[1]), "+f"((cr)[2]), "+f"((cr)[3])              \
        : "r"((a)[0]), "r"((a)[1]), "r"((a)[2]), "r"((a)[3]), "r"(b0), "r"(b1))

#define LDSM_X4(r0, r1, r2, r3, addr)                                             \
    asm volatile("ldmatrix.sync.aligned.m8n8.x4.shared.b16 {%0,%1,%2,%3}, [%4];"  \
        : "=r"(r0), "=r"(r1), "=r"(r2), "=r"(r3) : "r"(addr))

__device__ __forceinline__ uint32_t smem_u32(const void* p) {
    uint32_t a;
    asm("{ .reg .u64 t; cvta.to.shared.u64 t, %1; cvt.u32.u64 %0, t; }" : "=r"(a) : "l"(p));
    return a;
}

// -------------------- 1. normalize rows + bf16 split of z --------------------
__global__ void k_norm_rows(const float* __restrict__ p0, const float* __restrict__ p1,
                            const float* __restrict__ z0, const float* __restrict__ z1) {
    int r = blockIdx.x, t = threadIdx.x;
    const float* srcP = (r < BATCH ? p0 : p1) + (size_t)(r & (BATCH - 1)) * DD;
    const float* srcZ = (r < BATCH ? z0 : z1) + (size_t)(r & (BATCH - 1)) * DD;
    float vp = srcP[t], vz = srcZ[t];
    float sp = vp * vp, sz = vz * vz;
    #pragma unroll
    for (int o = 16; o; o >>= 1) {
        sp += __shfl_xor_sync(0xFFFFFFFFu, sp, o);
        sz += __shfl_xor_sync(0xFFFFFFFFu, sz, o);
    }
    __shared__ float wsP[4], wsZ[4];
    if ((t & 31) == 0) { wsP[t >> 5] = sp; wsZ[t >> 5] = sz; }
    __syncthreads();
    sp = wsP[0] + wsP[1] + wsP[2] + wsP[3];
    sz = wsZ[0] + wsZ[1] + wsZ[2] + wsZ[3];
    float zp = vp * (1.0f / sqrtf(sp));
    float zz = vz * (1.0f / sqrtf(sz));
    size_t o = (size_t)r * DD + t;
    g_pn[o] = zp;
    g_zn[o] = zz;
    __nv_bfloat16 h = __float2bfloat16(zz);
    g_ah[o] = h;
    g_al[o] = __float2bfloat16(zz - __bfloat162float(h));
}

// -------------------- 2. queue column inverse norms --------------------
__global__ void k_colnorm(const float* __restrict__ q) {
    int k = blockIdx.x * blockDim.x + threadIdx.x;
    const float* p = q + k;
    float s = 0.f;
    #pragma unroll 8
    for (int d = 0; d < DD; d++) {
        float v = p[(size_t)d * KQ];
        s = fmaf(v, v, s);
    }
    g_inv[k] = 1.0f / sqrtf(s);
}

// -------------------- 3. mma.sync split-bf16 GEMM + masked argmax --------------------
// dyn smem: AH[128][KS] AL[128][KS] BH[256][KS] BL[256][KS]  (bf16) = 208,896 B
#define SM_AH 0
#define SM_AL (128 * KS)
#define SM_BH (256 * KS)
#define SM_BL (512 * KS)
#define SM_DYN (768 * KS * 2)

__global__ void __launch_bounds__(256, 1) k_mma(const float* __restrict__ Q,
                                                const int* __restrict__ qid,
                                                const int* __restrict__ ids) {
    extern __shared__ uint16_t sm[];
    uint16_t* AH = sm + SM_AH;
    uint16_t* AL = sm + SM_AL;
    uint16_t* BH = sm + SM_BH;
    uint16_t* BL = sm + SM_BL;
    __shared__ float invs[NCOL];
    __shared__ int   qids[NCOL];
    __shared__ int   sIds[BATCH];
    __shared__ unsigned long long red[128][2];

    int t = threadIdx.x, lane = t & 31;
    int g = lane >> 2, q = lane & 3;
    int wid = t >> 5, wm = wid & 3, wn = wid >> 2;
    int bx = blockIdx.x, cn = bx * NCOL;

    invs[t] = g_inv[cn + t];
    qids[t] = qid[cn + t];
    sIds[t]       = ids[t];
    sIds[t + 256] = ids[t + 256];

    // ---- B tile: queue[0..127][cn..cn+255] fp32 -> bf16 hi/lo, layout [col][d] ----
    {
        int colc = (t & 63) * 4;
        int d0 = t >> 6;
        #pragma unroll 4
        for (int i = 0; i < 32; i++) {
            int d = d0 + i * 4;
            float4 v = *(const float4*)(Q + (size_t)d * KQ + cn + colc);
            float vv[4] = {v.x, v.y, v.z, v.w};
            #pragma unroll
            for (int j = 0; j < 4; j++) {
                uint16_t hb = bfbits(vv[j]);
                uint16_t lb = bfbits(vv[j] - bffloat(hb));
                BH[(colc + j) * KS + d] = hb;
                BL[(colc + j) * KS + d] = lb;
            }
        }
    }

    // ---- per-lane ldmatrix base addresses (byte offsets in shared space) ----
    // A x4: matrices (m0-7,k0-7),(m8-15,k0-7),(m0-7,k8-15),(m8-15,k8-15)
    //   lane l: row = wm*32 + (l&15), kofs = (l>>4)*8
    uint32_t aRowOff = (uint32_t)((wm * 32 + (lane & 15)) * KS + (lane >> 4) * 8) * 2;
    uint32_t aAddrH = smem_u32(AH) + aRowOff;
    uint32_t aAddrL = smem_u32(AL) + aRowOff;
    // B x4: matrices (n0-7,k0-7),(n0-7,k8-15),(n8-15,k0-7),(n8-15,k8-15) for nj pair
    //   lane l: row = wn*128 + ((l>>4)<<3) + (l&7), kofs = ((l>>3)&1)*8
    uint32_t bRowOff = (uint32_t)((wn * 128 + ((lane >> 4) << 3) + (lane & 7)) * KS +
                                  (((lane >> 3) & 1) << 3)) * 2;
    uint32_t bAddrH = smem_u32(BH) + bRowOff;
    uint32_t bAddrL = smem_u32(BL) + bRowOff;

    for (int rm = 0; rm < NRM; rm++) {
        __syncthreads();   // prev iteration's reads of A / red done; safe to overwrite
        // ---- A tile: rows rm*128..+127, [row][d] bf16 hi/lo ----
        {
            int row = t >> 1, half = t & 1;
            const uint4* sh = (const uint4*)(g_ah + (size_t)(rm * 128 + row) * DD + half * 64);
            const uint4* sl = (const uint4*)(g_al + (size_t)(rm * 128 + row) * DD + half * 64);
            uint4* dh = (uint4*)(AH + row * KS + half * 64);
            uint4* dl = (uint4*)(AL + row * KS + half * 64);
            #pragma unroll
            for (int i = 0; i < 8; i++) { dh[i] = sh[i]; dl[i] = sl[i]; }
        }
        __syncthreads();

        float c[2][16][4];
        #pragma unroll
        for (int mi = 0; mi < 2; mi++)
            #pragma unroll
            for (int nj = 0; nj < 16; nj++)
                #pragma unroll
                for (int cc = 0; cc < 4; cc++) c[mi][nj][cc] = 0.0f;

        #pragma unroll 1
        for (int ks = 0; ks < 8; ks++) {
            uint32_t ko = ks * 32;            // 16 bf16 = 32 bytes
            uint32_t ah[2][4], al[2][4];
            LDSM_X4(ah[0][0], ah[0][1], ah[0][2], ah[0][3], aAddrH + ko);
            LDSM_X4(ah[1][0], ah[1][1], ah[1][2], ah[1][3], aAddrH + 16 * KS * 2 + ko);
            LDSM_X4(al[0][0], al[0][1], al[0][2], al[0][3], aAddrL + ko);
            LDSM_X4(al[1][0], al[1][1], al[1][2], al[1][3], aAddrL + 16 * KS * 2 + ko);

            // pass 1: Ah * Bh
            #pragma unroll
            for (int p = 0; p < 8; p++) {
                uint32_t b0, b1, b2, b3;
                LDSM_X4(b0, b1, b2, b3, bAddrH + p * 16 * KS * 2 + ko);
                MMA_BF16(c[0][2 * p],     ah[0], b0, b1);
                MMA_BF16(c[1][2 * p],     ah[1], b0, b1);
                MMA_BF16(c[0][2 * p + 1], ah[0], b2, b3);
                MMA_BF16(c[1][2 * p + 1], ah[1], b2, b3);
            }
            // pass 2: Ah * Bl
            #pragma unroll
            for (int p = 0; p < 8; p++) {
                uint32_t b0, b1, b2, b3;
                LDSM_X4(b0, b1, b2, b3, bAddrL + p * 16 * KS * 2 + ko);
                MMA_BF16(c[0][2 * p],     ah[0], b0, b1);
                MMA_BF16(c[1][2 * p],     ah[1], b0, b1);
                MMA_BF16(c[0][2 * p + 1], ah[0], b2, b3);
                MMA_BF16(c[1][2 * p + 1], ah[1], b2, b3);
            }
            // pass 3: Al * Bh
            #pragma unroll
            for (int p = 0; p < 8; p++) {
                uint32_t b0, b1, b2, b3;
                LDSM_X4(b0, b1, b2, b3, bAddrH + p * 16 * KS * 2 + ko);
                MMA_BF16(c[0][2 * p],     al[0], b0, b1);
                MMA_BF16(c[1][2 * p],     al[1], b0, b1);
                MMA_BF16(c[0][2 * p + 1], al[0], b2, b3);
                MMA_BF16(c[1][2 * p + 1], al[1], b2, b3);
            }
        }

        // ---- epilogue: scale, mask, per-row argmax ----
        #pragma unroll
        for (int mi = 0; mi < 2; mi++) {
            #pragma unroll
            for (int rh = 0; rh < 2; rh++) {
                int lrow = wm * 32 + mi * 16 + rh * 8 + g;
                int id_i = sIds[(rm * 128 + lrow) & (BATCH - 1)];
                unsigned long long best = 0ull;
                #pragma unroll
                for (int nj = 0; nj < 16; nj++) {
                    #pragma unroll
                    for (int cc = 0; cc < 2; cc++) {
                        int col = wn * 128 + nj * 8 + 2 * q + cc;
                        float v = c[mi][nj][rh * 2 + cc] * invs[col];
                        if (qids[col] == id_i) v = -1.0f;
                        unsigned long long key =
                            ((unsigned long long)fkey(v) << 32) | (unsigned)(~(cn + col));
                        if (key > best) best = key;
                    }
                }
                unsigned long long o1 = __shfl_xor_sync(0xFFFFFFFFu, best, 1);
                if (o1 > best) best = o1;
                unsigned long long o2 = __shfl_xor_sync(0xFFFFFFFFu, best, 2);
                if (o2 > best) best = o2;
                if (q == 0) red[lrow][wn] = best;
            }
        }
        __syncthreads();
        if (t < 128) {
            unsigned long long b = red[t][0];
            if (red[t][1] > b) b = red[t][1];
            g_part[(size_t)(rm * 128 + t) * NTIL + bx] = b;
        }
    }
}

// -------------------- 4. reduce per-tile argmax partials --------------------
__global__ void k_argreduce() {
    int r = blockIdx.x, t = threadIdx.x;  // 256 threads, NTIL=512
    const unsigned long long* p = &g_part[(size_t)r * NTIL];
    unsigned long long b = p[t];
    unsigned long long v = p[t + 256];
    if (v > b) b = v;
    __shared__ unsigned long long s[256];
    s[t] = b;
    __syncthreads();
    for (int o = 128; o; o >>= 1) {
        if (t < o) { if (s[t + o] > s[t]) s[t] = s[t + o]; }
        __syncthreads();
    }
    if (t == 0) g_idx[r] = (int)(~(unsigned)s[0]);
}

// -------------------- 5. contrastive loss diag terms --------------------
__global__ void k_loss(const float* __restrict__ Q) {
    int b = blockIdx.x;
    int view = b >> 9;
    int i = b & (BATCH - 1);
    int t = threadIdx.x;  // 128

    int nidx = (view == 0) ? g_idx[BATCH + i] : g_idx[i];
    __shared__ float nn[128];
    nn[t] = Q[(size_t)t * KQ + nidx] * g_inv[nidx];
    __syncthreads();

    const float* p = g_pn + (size_t)view * BATCH * DD;
    float lg[4];
    float mx = -1e30f;
    #pragma unroll
    for (int jj = 0; jj < 4; jj++) {
        int j = t + jj * 128;
        const float4* pj = (const float4*)&p[(size_t)j * DD];
        float s = 0.f;
        #pragma unroll
        for (int d4 = 0; d4 < 32; d4++) {
            float4 pv = pj[d4];
            s = fmaf(nn[d4 * 4 + 0], pv.x, s);
            s = fmaf(nn[d4 * 4 + 1], pv.y, s);
            s = fmaf(nn[d4 * 4 + 2], pv.z, s);
            s = fmaf(nn[d4 * 4 + 3], pv.w, s);
        }
        lg[jj] = s * (1.0f / 0.07f);
        mx = fmaxf(mx, lg[jj]);
    }

    __shared__ float sm[128];
    __shared__ float sdiag;
    #pragma unroll
    for (int jj = 0; jj < 4; jj++)
        if (t + jj * 128 == i) sdiag = lg[jj];

    sm[t] = mx;
    for (int o = 64; o; o >>= 1) {
        __syncthreads();
        if (t < o) sm[t] = fmaxf(sm[t], sm[t + o]);
    }
    __syncthreads();
    float m = sm[0];
    __syncthreads();

    float se = 0.f;
    #pragma unroll
    for (int jj = 0; jj < 4; jj++) se += expf(lg[jj] - m);
    sm[t] = se;
    for (int o = 64; o; o >>= 1) {
        __syncthreads();
        if (t < o) sm[t] += sm[t + o];
    }
    __syncthreads();
    if (t == 0) g_loss[b] = -(sdiag - m - logf(sm[0]));
}

// -------------------- 6. final loss reduce --------------------
__global__ void k_lossred(float* __restrict__ out) {
    int t = threadIdx.x;  // 1024
    __shared__ float s[1024];
    s[t] = g_loss[t];
    __syncthreads();
    for (int o = 512; o; o >>= 1) {
        if (t < o) s[t] += s[t + o];
        __syncthreads();
    }
    if (t == 0) out[0] = s[0] * (1.0f / 1024.0f);
}

// -------------------- 7. write new_queue --------------------
__global__ void k_writeq(const float* __restrict__ Q, float* __restrict__ out) {
    size_t e = (size_t)blockIdx.x * blockDim.x + threadIdx.x;
    int k4 = (int)(e % (KQ / 4));
    int d  = (int)(e / (KQ / 4));
    int k  = k4 * 4;
    float x, y, z, w;
    if (k >= BATCH) {
        float4 qv = *(const float4*)&Q[(size_t)d * KQ + k];
        float4 iv = *(const float4*)&g_inv[k];
        x = qv.x * iv.x; y = qv.y * iv.y; z = qv.z * iv.z; w = qv.w * iv.w;
    } else {
        x = g_zn[(size_t)(k + 0) * DD + d];
        y = g_zn[(size_t)(k + 1) * DD + d];
        z = g_zn[(size_t)(k + 2) * DD + d];
        w = g_zn[(size_t)(k + 3) * DD + d];
    }
    size_t o = (size_t)d * KQ + k;   // out base is d_out+1 (4B aligned) -> scalar stores
    out[o] = x; out[o + 1] = y; out[o + 2] = z; out[o + 3] = w;
}

// -------------------- 8. write new_queue_id + new_ptr --------------------
__global__ void k_writeids(const int* __restrict__ qid, const int* __restrict__ ids,
                           float* __restrict__ out) {
    int k = blockIdx.x * blockDim.x + threadIdx.x;
    if (k < KQ) out[k] = (float)(k < BATCH ? ids[k] : qid[k]);
    if (k == 0) out[KQ] = (float)BATCH;  // (0 + 512) % 131072
}

// -------------------- launch --------------------
extern "C" void kernel_launch(void* const* d_in, const int* in_sizes, int n_in,
                              void* d_out, int out_size) {
    const float* predict0 = (const float*)d_in[0];
    const float* predict1 = (const float*)d_in[1];
    const float* project0 = (const float*)d_in[2];
    const float* project1 = (const float*)d_in[3];
    const float* queue    = (const float*)d_in[4];
    const int*   queue_id = (const int*)d_in[5];
    const int*   ids      = (const int*)d_in[6];
    float* out = (float*)d_out;

    cudaFuncSetAttribute(k_mma, cudaFuncAttributeMaxDynamicSharedMemorySize, SM_DYN);

    k_norm_rows<<<RR, 128>>>(predict0, predict1, project0, project1);
    k_colnorm<<<KQ / 256, 256>>>(queue);
    k_mma<<<NTIL, 256, SM_DYN>>>(queue, queue_id, ids);
    k_argreduce<<<RR, 256>>>();
    k_loss<<<RR, 128>>>(queue);
    k_lossred<<<1, 1024>>>(out);
    k_writeq<<<((size_t)DD * KQ / 4) / 256, 256>>>(queue, out + 1);
    k_writeids<<<KQ / 256, 256>>>(queue_id, ids, out + 1 + (size_t)DD * KQ);
}

// round 10
// speedup vs baseline: 1.5629x; 1.5560x over previous
#include <cuda_runtime.h>
#include <cuda_bf16.h>
#include <math.h>
#include <stdint.h>

// Problem constants
#define BATCH 512
#define DD    128
#define KQ    131072
#define RR    1024           // 2 views * BATCH rows
#define NCOL  256            // queue cols per CTA
#define NTIL  (KQ / NCOL)    // 512 col tiles
#define NSUB  (KQ / 32)      // 4096 32-col subtiles
#define NRM   (RR / 128)     // 8 row tiles per CTA loop
#define KS    136            // smem row stride in bf16 units (272B, conflict-free)
#define MARGIN 0.008f        // 2*2^-8 + slack: worst-case bf16 rounding bound

// -------------------- device scratch --------------------
__device__ float              g_zn[RR * DD];
__device__ float              g_pn[RR * DD];
__device__ __nv_bfloat16      g_ah[RR * DD];     // bf16 of normalized z
__device__ float              g_inv[KQ];
__device__ unsigned long long g_part[(size_t)RR * NSUB];  // per (row, 32-col subtile) top key
__device__ float              g_m1[RR];          // phase-1 max sim per row
__device__ int                g_idx[RR];
__device__ float              g_loss[RR];

__device__ __forceinline__ unsigned fkey(float f) {
    unsigned u = __float_as_uint(f);
    unsigned m = (unsigned)(((int)u) >> 31);
    return u ^ (m | 0x80000000u);
}
__device__ __forceinline__ float fdec(unsigned k) {
    return __uint_as_float((k & 0x80000000u) ? (k ^ 0x80000000u) : ~k);
}

#define MMA_BF16(cr, a, b0, b1)                                                   \
    asm volatile("mma.sync.aligned.m16n8k16.row.col.f32.bf16.bf16.f32 "           \
        "{%0,%1,%2,%3}, {%4,%5,%6,%7}, {%8,%9}, {%0,%1,%2,%3};"                   \
        : "+f"((cr)[0]), "+f"((cr)[1]), "+f"((cr)[2]), "+f"((cr)[3])              \
        : "r"((a)[0]), "r"((a)[1]), "r"((a)[2]), "r"((a)[3]), "r"(b0), "r"(b1))

#define LDSM_X4(r0, r1, r2, r3, addr)                                             \
    asm volatile("ldmatrix.sync.aligned.m8n8.x4.shared.b16 {%0,%1,%2,%3}, [%4];"  \
        : "=r"(r0), "=r"(r1), "=r"(r2), "=r"(r3) : "r"(addr))

__device__ __forceinline__ uint32_t smem_u32(const void* p) {
    uint32_t a;
    asm("{ .reg .u64 t; cvta.to.shared.u64 t, %1; cvt.u32.u64 %0, t; }" : "=r"(a) : "l"(p));
    return a;
}

// -------------------- 1. normalize rows + bf16 of z --------------------
__global__ void k_norm_rows(const float* __restrict__ p0, const float* __restrict__ p1,
                            const float* __restrict__ z0, const float* __restrict__ z1) {
    int r = blockIdx.x, t = threadIdx.x;
    const float* srcP = (r < BATCH ? p0 : p1) + (size_t)(r & (BATCH - 1)) * DD;
    const float* srcZ = (r < BATCH ? z0 : z1) + (size_t)(r & (BATCH - 1)) * DD;
    float vp = srcP[t], vz = srcZ[t];
    float sp = vp * vp, sz = vz * vz;
    #pragma unroll
    for (int o = 16; o; o >>= 1) {
        sp += __shfl_xor_sync(0xFFFFFFFFu, sp, o);
        sz += __shfl_xor_sync(0xFFFFFFFFu, sz, o);
    }
    __shared__ float wsP[4], wsZ[4];
    if ((t & 31) == 0) { wsP[t >> 5] = sp; wsZ[t >> 5] = sz; }
    __syncthreads();
    sp = wsP[0] + wsP[1] + wsP[2] + wsP[3];
    sz = wsZ[0] + wsZ[1] + wsZ[2] + wsZ[3];
    float zp = vp * (1.0f / sqrtf(sp));
    float zz = vz * (1.0f / sqrtf(sz));
    size_t o = (size_t)r * DD + t;
    g_pn[o] = zp;
    g_zn[o] = zz;
    g_ah[o] = __float2bfloat16(zz);
}

// -------------------- 2. queue column inverse norms --------------------
__global__ void k_colnorm(const float* __restrict__ q) {
    int k = blockIdx.x * blockDim.x + threadIdx.x;
    const float* p = q + k;
    float s = 0.f;
    #pragma unroll 8
    for (int d = 0; d < DD; d++) {
        float v = p[(size_t)d * KQ];
        s = fmaf(v, v, s);
    }
    g_inv[k] = 1.0f / sqrtf(s);
}

// -------------------- 3. single-pass bf16 GEMM + per-subtile argmax --------------------
// dyn smem: AH[128][KS] BH[256][KS] (bf16) = 104,448 B
#define SM_AH 0
#define SM_BH (128 * KS)
#define SM_DYN (384 * KS * 2)

__global__ void __launch_bounds__(256, 1) k_mma(const float* __restrict__ Q,
                                                const int* __restrict__ qid,
                                                const int* __restrict__ ids) {
    extern __shared__ uint16_t sm[];
    uint16_t* AH = sm + SM_AH;
    uint16_t* BH = sm + SM_BH;
    __shared__ float invs[NCOL];
    __shared__ int   qids[NCOL];
    __shared__ int   sIds[BATCH];

    int t = threadIdx.x, lane = t & 31;
    int g = lane >> 2, q = lane & 3;
    int wid = t >> 5, wm = wid & 3, wn = wid >> 2;
    int bx = blockIdx.x, cn = bx * NCOL;

    invs[t] = g_inv[cn + t];
    qids[t] = qid[cn + t];
    sIds[t]       = ids[t];
    sIds[t + 256] = ids[t + 256];

    // ---- B tile: queue[0..127][cn..cn+255] fp32 -> bf16, layout [col][d] ----
    {
        int colc = (t & 63) * 4;
        int d0 = t >> 6;
        #pragma unroll 4
        for (int i = 0; i < 32; i++) {
            int d = d0 + i * 4;
            float4 v = *(const float4*)(Q + (size_t)d * KQ + cn + colc);
            __nv_bfloat16 b0 = __float2bfloat16(v.x);
            __nv_bfloat16 b1 = __float2bfloat16(v.y);
            __nv_bfloat16 b2 = __float2bfloat16(v.z);
            __nv_bfloat16 b3 = __float2bfloat16(v.w);
            BH[(colc + 0) * KS + d] = *(uint16_t*)&b0;
            BH[(colc + 1) * KS + d] = *(uint16_t*)&b1;
            BH[(colc + 2) * KS + d] = *(uint16_t*)&b2;
            BH[(colc + 3) * KS + d] = *(uint16_t*)&b3;
        }
    }

    // ---- per-lane ldmatrix base addresses ----
    uint32_t aRowOff = (uint32_t)((wm * 32 + (lane & 15)) * KS + (lane >> 4) * 8) * 2;
    uint32_t aAddrH = smem_u32(AH) + aRowOff;
    uint32_t bRowOff = (uint32_t)((wn * 128 + ((lane >> 4) << 3) + (lane & 7)) * KS +
                                  (((lane >> 3) & 1) << 3)) * 2;
    uint32_t bAddrH = smem_u32(BH) + bRowOff;

    for (int rm = 0; rm < NRM; rm++) {
        __syncthreads();   // prev iteration's AH reads done
        // ---- A tile: rows rm*128..+127, [row][d] bf16 ----
        {
            int row = t >> 1, half = t & 1;
            const uint4* sh = (const uint4*)(g_ah + (size_t)(rm * 128 + row) * DD + half * 64);
            uint4* dh = (uint4*)(AH + row * KS + half * 64);
            #pragma unroll
            for (int i = 0; i < 8; i++) dh[i] = sh[i];
        }
        __syncthreads();

        float c[2][16][4];
        #pragma unroll
        for (int mi = 0; mi < 2; mi++)
            #pragma unroll
            for (int nj = 0; nj < 16; nj++)
                #pragma unroll
                for (int cc = 0; cc < 4; cc++) c[mi][nj][cc] = 0.0f;

        #pragma unroll 1
        for (int ks = 0; ks < 8; ks++) {
            uint32_t ko = ks * 32;            // 16 bf16 = 32 bytes
            uint32_t ah[2][4];
            LDSM_X4(ah[0][0], ah[0][1], ah[0][2], ah[0][3], aAddrH + ko);
            LDSM_X4(ah[1][0], ah[1][1], ah[1][2], ah[1][3], aAddrH + 16 * KS * 2 + ko);
            #pragma unroll
            for (int p = 0; p < 8; p++) {
                uint32_t b0, b1, b2, b3;
                LDSM_X4(b0, b1, b2, b3, bAddrH + p * 16 * KS * 2 + ko);
                MMA_BF16(c[0][2 * p],     ah[0], b0, b1);
                MMA_BF16(c[1][2 * p],     ah[1], b0, b1);
                MMA_BF16(c[0][2 * p + 1], ah[0], b2, b3);
                MMA_BF16(c[1][2 * p + 1], ah[1], b2, b3);
            }
        }

        // ---- epilogue: scale, mask, per-32col-subtile argmax ----
        #pragma unroll
        for (int mi = 0; mi < 2; mi++) {
            #pragma unroll
            for (int rh = 0; rh < 2; rh++) {
                int lrow = wm * 32 + mi * 16 + rh * 8 + g;
                int row = rm * 128 + lrow;
                int id_i = sIds[row & (BATCH - 1)];
                #pragma unroll
                for (int grp = 0; grp < 4; grp++) {
                    unsigned long long best = 0ull;
                    #pragma unroll
                    for (int j = 0; j < 4; j++) {
                        int nj = grp * 4 + j;
                        #pragma unroll
                        for (int cc = 0; cc < 2; cc++) {
                            int col = wn * 128 + nj * 8 + 2 * q + cc;
                            float v = c[mi][nj][rh * 2 + cc] * invs[col];
                            if (qids[col] == id_i) v = -1.0f;
                            unsigned long long key =
                                ((unsigned long long)fkey(v) << 32) | (unsigned)(~(cn + col));
                            if (key > best) best = key;
                        }
                    }
                    unsigned long long o1 = __shfl_xor_sync(0xFFFFFFFFu, best, 1);
                    if (o1 > best) best = o1;
                    unsigned long long o2 = __shfl_xor_sync(0xFFFFFFFFu, best, 2);
                    if (o2 > best) best = o2;
                    if (q == 0)
                        g_part[(size_t)row * NSUB + bx * 8 + wn * 4 + grp] = best;
                }
            }
        }
    }
}

// -------------------- 4. reduce per-subtile keys -> phase-1 max --------------------
__global__ void k_argreduce() {
    int r = blockIdx.x, t = threadIdx.x;  // 256 threads
    const unsigned long long* p = &g_part[(size_t)r * NSUB];
    unsigned long long b = 0ull;
    #pragma unroll 4
    for (int j = t; j < NSUB; j += 256) {
        unsigned long long v = p[j];
        if (v > b) b = v;
    }
    __shared__ unsigned long long s[256];
    s[t] = b;
    __syncthreads();
    for (int o = 128; o; o >>= 1) {
        if (t < o) { if (s[t + o] > s[t]) s[t] = s[t + o]; }
        __syncthreads();
    }
    if (t == 0) g_m1[r] = fdec((unsigned)(s[0] >> 32));
}

// -------------------- 4b. exact refinement of candidate subtiles --------------------
__global__ void __launch_bounds__(128) k_refine(const float* __restrict__ Q,
                                                const int* __restrict__ qid,
                                                const int* __restrict__ ids) {
    int r = blockIdx.x, t = threadIdx.x;  // 128 threads
    __shared__ float zrow[DD];
    __shared__ int list[NSUB];
    __shared__ int cnt;
    __shared__ float part[4][32];
    __shared__ unsigned long long sbest;
    if (t == 0) { cnt = 0; sbest = 0ull; }
    zrow[t] = g_zn[(size_t)r * DD + t];
    __syncthreads();

    float thr = g_m1[r] - MARGIN;
    const unsigned long long* pp = &g_part[(size_t)r * NSUB];
    for (int j = t; j < NSUB; j += 128) {
        float v = fdec((unsigned)(pp[j] >> 32));
        if (v >= thr) { int s = atomicAdd(&cnt, 1); list[s] = j; }
    }
    __syncthreads();

    int n = cnt;
    int id_i = ids[r & (BATCH - 1)];
    int colt = t & 31, seg = t >> 5;

    for (int s = 0; s < n; s++) {
        int col0 = list[s] * 32;
        float acc = 0.f;
        const float* qp = Q + (size_t)(seg * 32) * KQ + col0 + colt;
        #pragma unroll 8
        for (int d = 0; d < 32; d++)
            acc = fmaf(zrow[seg * 32 + d], qp[(size_t)d * KQ], acc);
        part[seg][colt] = acc;
        __syncthreads();
        if (t < 32) {
            int col = col0 + t;
            float simv = (part[0][t] + part[1][t] + part[2][t] + part[3][t]) * g_inv[col];
            if (qid[col] == id_i) simv = -1.0f;
            unsigned long long key =
                ((unsigned long long)fkey(simv) << 32) | (unsigned)(~col);
            #pragma unroll
            for (int o = 16; o; o >>= 1) {
                unsigned long long ok = __shfl_xor_sync(0xFFFFFFFFu, key, o);
                if (ok > key) key = ok;
            }
            if (t == 0 && key > sbest) sbest = key;
        }
        __syncthreads();
    }
    if (t == 0) g_idx[r] = (int)(~(unsigned)sbest);
}

// -------------------- 5. contrastive loss diag terms --------------------
__global__ void k_loss(const float* __restrict__ Q) {
    int b = blockIdx.x;
    int view = b >> 9;
    int i = b & (BATCH - 1);
    int t = threadIdx.x;  // 128

    int nidx = (view == 0) ? g_idx[BATCH + i] : g_idx[i];
    __shared__ float nn[128];
    nn[t] = Q[(size_t)t * KQ + nidx] * g_inv[nidx];
    __syncthreads();

    const float* p = g_pn + (size_t)view * BATCH * DD;
    float lg[4];
    float mx = -1e30f;
    #pragma unroll
    for (int jj = 0; jj < 4; jj++) {
        int j = t + jj * 128;
        const float4* pj = (const float4*)&p[(size_t)j * DD];
        float s = 0.f;
        #pragma unroll
        for (int d4 = 0; d4 < 32; d4++) {
            float4 pv = pj[d4];
            s = fmaf(nn[d4 * 4 + 0], pv.x, s);
            s = fmaf(nn[d4 * 4 + 1], pv.y, s);
            s = fmaf(nn[d4 * 4 + 2], pv.z, s);
            s = fmaf(nn[d4 * 4 + 3], pv.w, s);
        }
        lg[jj] = s * (1.0f / 0.07f);
        mx = fmaxf(mx, lg[jj]);
    }

    __shared__ float sm[128];
    __shared__ float sdiag;
    #pragma unroll
    for (int jj = 0; jj < 4; jj++)
        if (t + jj * 128 == i) sdiag = lg[jj];

    sm[t] = mx;
    for (int o = 64; o; o >>= 1) {
        __syncthreads();
        if (t < o) sm[t] = fmaxf(sm[t], sm[t + o]);
    }
    __syncthreads();
    float m = sm[0];
    __syncthreads();

    float se = 0.f;
    #pragma unroll
    for (int jj = 0; jj < 4; jj++) se += expf(lg[jj] - m);
    sm[t] = se;
    for (int o = 64; o; o >>= 1) {
        __syncthreads();
        if (t < o) sm[t] += sm[t + o];
    }
    __syncthreads();
    if (t == 0) g_loss[b] = -(sdiag - m - logf(sm[0]));
}

// -------------------- 6. final loss reduce --------------------
__global__ void k_lossred(float* __restrict__ out) {
    int t = threadIdx.x;  // 1024
    __shared__ float s[1024];
    s[t] = g_loss[t];
    __syncthreads();
    for (int o = 512; o; o >>= 1) {
        if (t < o) s[t] += s[t + o];
        __syncthreads();
    }
    if (t == 0) out[0] = s[0] * (1.0f / 1024.0f);
}

// -------------------- 7. write new_queue --------------------
__global__ void k_writeq(const float* __restrict__ Q, float* __restrict__ out) {
    size_t e = (size_t)blockIdx.x * blockDim.x + threadIdx.x;
    int k4 = (int)(e % (KQ / 4));
    int d  = (int)(e / (KQ / 4));
    int k  = k4 * 4;
    float x, y, z, w;
    if (k >= BATCH) {
        float4 qv = *(const float4*)&Q[(size_t)d * KQ + k];
        float4 iv = *(const float4*)&g_inv[k];
        x = qv.x * iv.x; y = qv.y * iv.y; z = qv.z * iv.z; w = qv.w * iv.w;
    } else {
        x = g_zn[(size_t)(k + 0) * DD + d];
        y = g_zn[(size_t)(k + 1) * DD + d];
        z = g_zn[(size_t)(k + 2) * DD + d];
        w = g_zn[(size_t)(k + 3) * DD + d];
    }
    size_t o = (size_t)d * KQ + k;   // out base is d_out+1 (4B aligned) -> scalar stores
    out[o] = x; out[o + 1] = y; out[o + 2] = z; out[o + 3] = w;
}

// -------------------- 8. write new_queue_id + new_ptr --------------------
__global__ void k_writeids(const int* __restrict__ qid, const int* __restrict__ ids,
                           float* __restrict__ out) {
    int k = blockIdx.x * blockDim.x + threadIdx.x;
    if (k < KQ) out[k] = (float)(k < BATCH ? ids[k] : qid[k]);
    if (k == 0) out[KQ] = (float)BATCH;  // (0 + 512) % 131072
}

// -------------------- launch --------------------
extern "C" void kernel_launch(void* const* d_in, const int* in_sizes, int n_in,
                              void* d_out, int out_size) {
    const float* predict0 = (const float*)d_in[0];
    const float* predict1 = (const float*)d_in[1];
    const float* project0 = (const float*)d_in[2];
    const float* project1 = (const float*)d_in[3];
    const float* queue    = (const float*)d_in[4];
    const int*   queue_id = (const int*)d_in[5];
    const int*   ids      = (const int*)d_in[6];
    float* out = (float*)d_out;

    cudaFuncSetAttribute(k_mma, cudaFuncAttributeMaxDynamicSharedMemorySize, SM_DYN);

    k_norm_rows<<<RR, 128>>>(predict0, predict1, project0, project1);
    k_colnorm<<<KQ / 256, 256>>>(queue);
    k_mma<<<NTIL, 256, SM_DYN>>>(queue, queue_id, ids);
    k_argreduce<<<RR, 256>>>();
    k_refine<<<RR, 128>>>(queue, queue_id, ids);
    k_loss<<<RR, 128>>>(queue);
    k_lossred<<<1, 1024>>>(out);
    k_writeq<<<((size_t)DD * KQ / 4) / 256, 256>>>(queue, out + 1);
    k_writeids<<<KQ / 256, 256>>>(queue_id, ids, out + 1 + (size_t)DD * KQ);
}

// round 12
// speedup vs baseline: 1.7901x; 1.1453x over previous
#include <cuda_runtime.h>
#include <cuda_bf16.h>
#include <math.h>
#include <stdint.h>

// Problem constants
#define BATCH 512
#define DD    128
#define KQ    131072
#define RR    1024           // 2 views * BATCH rows
#define NCOL  256            // queue cols per CTA
#define NTIL  (KQ / NCOL)    // 512 col tiles
#define NSUB  (KQ / 32)      // 4096 32-col subtiles
#define NRM   (RR / 128)     // 8 row tiles per CTA loop
#define KS    136            // smem row stride in bf16 units (272B, conflict-free)
#define MARGIN 0.008f        // worst-case bf16 rounding bound (~0.004) + 2x slack

// -------------------- device scratch --------------------
__device__ float              g_zn[RR * DD];
__device__ float              g_pn[RR * DD];
__device__ __nv_bfloat16      g_ah[RR * DD];     // bf16 of normalized z
__device__ float              g_inv[KQ];
__device__ float              g_part[(size_t)RR * NSUB];  // per (row, 32-col subtile) max sim (16MB)
__device__ float              g_m1[RR];          // phase-1 max sim per row
__device__ int                g_idx[RR];
__device__ float              g_loss[RR];

__device__ __forceinline__ unsigned fkey(float f) {
    unsigned u = __float_as_uint(f);
    unsigned m = (unsigned)(((int)u) >> 31);
    return u ^ (m | 0x80000000u);
}

#define MMA_BF16(cr, a, b0, b1)                                                   \
    asm volatile("mma.sync.aligned.m16n8k16.row.col.f32.bf16.bf16.f32 "           \
        "{%0,%1,%2,%3}, {%4,%5,%6,%7}, {%8,%9}, {%0,%1,%2,%3};"                   \
        : "+f"((cr)[0]), "+f"((cr)[1]), "+f"((cr)[2]), "+f"((cr)[3])              \
        : "r"((a)[0]), "r"((a)[1]), "r"((a)[2]), "r"((a)[3]), "r"(b0), "r"(b1))

#define LDSM_X4(r0, r1, r2, r3, addr)                                             \
    asm volatile("ldmatrix.sync.aligned.m8n8.x4.shared.b16 {%0,%1,%2,%3}, [%4];"  \
        : "=r"(r0), "=r"(r1), "=r"(r2), "=r"(r3) : "r"(addr))

__device__ __forceinline__ uint32_t smem_u32(const void* p) {
    uint32_t a;
    asm("{ .reg .u64 t; cvta.to.shared.u64 t, %1; cvt.u32.u64 %0, t; }" : "=r"(a) : "l"(p));
    return a;
}

// -------------------- 1. normalize rows + bf16 of z --------------------
__global__ void k_norm_rows(const float* __restrict__ p0, const float* __restrict__ p1,
                            const float* __restrict__ z0, const float* __restrict__ z1) {
    int r = blockIdx.x, t = threadIdx.x;
    const float* srcP = (r < BATCH ? p0 : p1) + (size_t)(r & (BATCH - 1)) * DD;
    const float* srcZ = (r < BATCH ? z0 : z1) + (size_t)(r & (BATCH - 1)) * DD;
    float vp = srcP[t], vz = srcZ[t];
    float sp = vp * vp, sz = vz * vz;
    #pragma unroll
    for (int o = 16; o; o >>= 1) {
        sp += __shfl_xor_sync(0xFFFFFFFFu, sp, o);
        sz += __shfl_xor_sync(0xFFFFFFFFu, sz, o);
    }
    __shared__ float wsP[4], wsZ[4];
    if ((t & 31) == 0) { wsP[t >> 5] = sp; wsZ[t >> 5] = sz; }
    __syncthreads();
    sp = wsP[0] + wsP[1] + wsP[2] + wsP[3];
    sz = wsZ[0] + wsZ[1] + wsZ[2] + wsZ[3];
    float zp = vp * (1.0f / sqrtf(sp));
    float zz = vz * (1.0f / sqrtf(sz));
    size_t o = (size_t)r * DD + t;
    g_pn[o] = zp;
    g_zn[o] = zz;
    g_ah[o] = __float2bfloat16(zz);
}

// -------------------- 2. queue column inverse norms --------------------
__global__ void k_colnorm(const float* __restrict__ q) {
    int k = blockIdx.x * blockDim.x + threadIdx.x;
    const float* p = q + k;
    float s = 0.f;
    #pragma unroll 8
    for (int d = 0; d < DD; d++) {
        float v = p[(size_t)d * KQ];
        s = fmaf(v, v, s);
    }
    g_inv[k] = 1.0f / sqrtf(s);
}

// -------------------- 3. single-pass bf16 GEMM (pre-scaled B) + per-subtile max --------------------
// dyn smem: AH[128][KS] BH[256][KS] (bf16) = 104,448 B
#define SM_AH 0
#define SM_BH (128 * KS)
#define SM_DYN (384 * KS * 2)

__global__ void __launch_bounds__(256, 1) k_mma(const float* __restrict__ Q,
                                                const int* __restrict__ qid,
                                                const int* __restrict__ ids) {
    extern __shared__ uint16_t sm[];
    uint16_t* AH = sm + SM_AH;
    uint16_t* BH = sm + SM_BH;
    __shared__ int qids[NCOL];
    __shared__ int sIds[BATCH];

    int t = threadIdx.x, lane = t & 31;
    int g = lane >> 2, q = lane & 3;
    int wid = t >> 5, wm = wid & 3, wn = wid >> 2;
    int bx = blockIdx.x, cn = bx * NCOL;

    qids[t] = qid[cn + t];
    sIds[t]       = ids[t];
    sIds[t + 256] = ids[t + 256];

    // ---- B tile: queue[0..127][cn..cn+255] fp32 * inv_norm -> bf16, layout [col][d] ----
    {
        int colc = (t & 63) * 4;
        int d0 = t >> 6;
        float iv0 = g_inv[cn + colc + 0];
        float iv1 = g_inv[cn + colc + 1];
        float iv2 = g_inv[cn + colc + 2];
        float iv3 = g_inv[cn + colc + 3];
        #pragma unroll 4
        for (int i = 0; i < 32; i++) {
            int d = d0 + i * 4;
            float4 v = *(const float4*)(Q + (size_t)d * KQ + cn + colc);
            __nv_bfloat16 b0 = __float2bfloat16(v.x * iv0);
            __nv_bfloat16 b1 = __float2bfloat16(v.y * iv1);
            __nv_bfloat16 b2 = __float2bfloat16(v.z * iv2);
            __nv_bfloat16 b3 = __float2bfloat16(v.w * iv3);
            BH[(colc + 0) * KS + d] = *(uint16_t*)&b0;
            BH[(colc + 1) * KS + d] = *(uint16_t*)&b1;
            BH[(colc + 2) * KS + d] = *(uint16_t*)&b2;
            BH[(colc + 3) * KS + d] = *(uint16_t*)&b3;
        }
    }

    // ---- per-lane ldmatrix base addresses ----
    uint32_t aRowOff = (uint32_t)((wm * 32 + (lane & 15)) * KS + (lane >> 4) * 8) * 2;
    uint32_t aAddrH = smem_u32(AH) + aRowOff;
    uint32_t bRowOff = (uint32_t)((wn * 128 + ((lane >> 4) << 3) + (lane & 7)) * KS +
                                  (((lane >> 3) & 1) << 3)) * 2;
    uint32_t bAddrH = smem_u32(BH) + bRowOff;

    for (int rm = 0; rm < NRM; rm++) {
        __syncthreads();   // prev iteration's AH reads done
        // ---- A tile: rows rm*128..+127, [row][d] bf16 ----
        {
            int row = t >> 1, half = t & 1;
            const uint4* sh = (const uint4*)(g_ah + (size_t)(rm * 128 + row) * DD + half * 64);
            uint4* dh = (uint4*)(AH + row * KS + half * 64);
            #pragma unroll
            for (int i = 0; i < 8; i++) dh[i] = sh[i];
        }
        __syncthreads();

        float c[2][16][4];
        #pragma unroll
        for (int mi = 0; mi < 2; mi++)
            #pragma unroll
            for (int nj = 0; nj < 16; nj++)
                #pragma unroll
                for (int cc = 0; cc < 4; cc++) c[mi][nj][cc] = 0.0f;

        #pragma unroll 1
        for (int ks = 0; ks < 8; ks++) {
            uint32_t ko = ks * 32;            // 16 bf16 = 32 bytes
            uint32_t ah[2][4];
            LDSM_X4(ah[0][0], ah[0][1], ah[0][2], ah[0][3], aAddrH + ko);
            LDSM_X4(ah[1][0], ah[1][1], ah[1][2], ah[1][3], aAddrH + 16 * KS * 2 + ko);
            #pragma unroll
            for (int p = 0; p < 8; p++) {
                uint32_t b0, b1, b2, b3;
                LDSM_X4(b0, b1, b2, b3, bAddrH + p * 16 * KS * 2 + ko);
                MMA_BF16(c[0][2 * p],     ah[0], b0, b1);
                MMA_BF16(c[1][2 * p],     ah[1], b0, b1);
                MMA_BF16(c[0][2 * p + 1], ah[0], b2, b3);
                MMA_BF16(c[1][2 * p + 1], ah[1], b2, b3);
            }
        }

        // ---- epilogue: mask, per-32col-subtile float max ----
        #pragma unroll
        for (int mi = 0; mi < 2; mi++) {
            #pragma unroll
            for (int rh = 0; rh < 2; rh++) {
                int lrow = wm * 32 + mi * 16 + rh * 8 + g;
                int row = rm * 128 + lrow;
                int id_i = sIds[row & (BATCH - 1)];
                #pragma unroll
                for (int grp = 0; grp < 4; grp++) {
                    float best = -2.0f;
                    #pragma unroll
                    for (int j = 0; j < 4; j++) {
                        int nj = grp * 4 + j;
                        #pragma unroll
                        for (int cc = 0; cc < 2; cc++) {
                            int col = wn * 128 + nj * 8 + 2 * q + cc;
                            float v = c[mi][nj][rh * 2 + cc];
                            if (qids[col] == id_i) v = -1.0f;
                            best = fmaxf(best, v);
                        }
                    }
                    best = fmaxf(best, __shfl_xor_sync(0xFFFFFFFFu, best, 1));
                    best = fmaxf(best, __shfl_xor_sync(0xFFFFFFFFu, best, 2));
                    if (q == 0)
                        g_part[(size_t)row * NSUB + bx * 8 + wn * 4 + grp] = best;
                }
            }
        }
    }
}

// -------------------- 4. reduce per-subtile maxima -> phase-1 row max --------------------
__global__ void k_argreduce() {
    int r = blockIdx.x, t = threadIdx.x;  // 256 threads
    const float* p = &g_part[(size_t)r * NSUB];
    float b = -2.0f;
    #pragma unroll 4
    for (int j = t; j < NSUB; j += 256) b = fmaxf(b, p[j]);
    __shared__ float s[256];
    s[t] = b;
    __syncthreads();
    for (int o = 128; o; o >>= 1) {
        if (t < o) s[t] = fmaxf(s[t], s[t + o]);
        __syncthreads();
    }
    if (t == 0) g_m1[r] = s[0];
}

// -------------------- 4b. exact refinement of candidate subtiles --------------------
__global__ void __launch_bounds__(128) k_refine(const float* __restrict__ Q,
                                                const int* __restrict__ qid,
                                                const int* __restrict__ ids) {
    int r = blockIdx.x, t = threadIdx.x;  // 128 threads
    __shared__ float zrow[DD];
    __shared__ int list[NSUB];
    __shared__ int cnt;
    __shared__ float part[4][32];
    __shared__ unsigned long long sbest;
    if (t == 0) { cnt = 0; sbest = 0ull; }
    zrow[t] = g_zn[(size_t)r * DD + t];
    __syncthreads();

    float thr = g_m1[r] - MARGIN;
    const float* pp = &g_part[(size_t)r * NSUB];
    for (int j = t; j < NSUB; j += 128) {
        if (pp[j] >= thr) { int s = atomicAdd(&cnt, 1); list[s] = j; }
    }
    __syncthreads();

    int n = cnt;
    int id_i = ids[r & (BATCH - 1)];
    int colt = t & 31, seg = t >> 5;

    for (int s = 0; s < n; s++) {
        int col0 = list[s] * 32;
        float acc = 0.f;
        const float* qp = Q + (size_t)(seg * 32) * KQ + col0 + colt;
        #pragma unroll 8
        for (int d = 0; d < 32; d++)
            acc = fmaf(zrow[seg * 32 + d], qp[(size_t)d * KQ], acc);
        part[seg][colt] = acc;
        __syncthreads();
        if (t < 32) {
            int col = col0 + t;
            float simv = (part[0][t] + part[1][t] + part[2][t] + part[3][t]) * g_inv[col];
            if (qid[col] == id_i) simv = -1.0f;
            unsigned long long key =
                ((unsigned long long)fkey(simv) << 32) | (unsigned)(~col);
            #pragma unroll
            for (int o = 16; o; o >>= 1) {
                unsigned long long ok = __shfl_xor_sync(0xFFFFFFFFu, key, o);
                if (ok > key) key = ok;
            }
            if (t == 0 && key > sbest) sbest = key;
        }
        __syncthreads();
    }
    if (t == 0) g_idx[r] = (int)(~(unsigned)sbest);
}

// -------------------- 5. contrastive loss diag terms --------------------
__global__ void k_loss(const float* __restrict__ Q) {
    int b = blockIdx.x;
    int view = b >> 9;
    int i = b & (BATCH - 1);
    int t = threadIdx.x;  // 128

    int nidx = (view == 0) ? g_idx[BATCH + i] : g_idx[i];
    __shared__ float nn[128];
    nn[t] = Q[(size_t)t * KQ + nidx] * g_inv[nidx];
    __syncthreads();

    const float* p = g_pn + (size_t)view * BATCH * DD;
    float lg[4];
    float mx = -1e30f;
    #pragma unroll
    for (int jj = 0; jj < 4; jj++) {
        int j = t + jj * 128;
        const float4* pj = (const float4*)&p[(size_t)j * DD];
        float s = 0.f;
        #pragma unroll
        for (int d4 = 0; d4 < 32; d4++) {
            float4 pv = pj[d4];
            s = fmaf(nn[d4 * 4 + 0], pv.x, s);
            s = fmaf(nn[d4 * 4 + 1], pv.y, s);
            s = fmaf(nn[d4 * 4 + 2], pv.z, s);
            s = fmaf(nn[d4 * 4 + 3], pv.w, s);
        }
        lg[jj] = s * (1.0f / 0.07f);
        mx = fmaxf(mx, lg[jj]);
    }

    __shared__ float sm[128];
    __shared__ float sdiag;
    #pragma unroll
    for (int jj = 0; jj < 4; jj++)
        if (t + jj * 128 == i) sdiag = lg[jj];

    sm[t] = mx;
    for (int o = 64; o; o >>= 1) {
        __syncthreads();
        if (t < o) sm[t] = fmaxf(sm[t], sm[t + o]);
    }
    __syncthreads();
    float m = sm[0];
    __syncthreads();

    float se = 0.f;
    #pragma unroll
    for (int jj = 0; jj < 4; jj++) se += expf(lg[jj] - m);
    sm[t] = se;
    for (int o = 64; o; o >>= 1) {
        __syncthreads();
        if (t < o) sm[t] += sm[t + o];
    }
    __syncthreads();
    if (t == 0) g_loss[b] = -(sdiag - m - logf(sm[0]));
}

// -------------------- 6. final loss reduce --------------------
__global__ void k_lossred(float* __restrict__ out) {
    int t = threadIdx.x;  // 1024
    __shared__ float s[1024];
    s[t] = g_loss[t];
    __syncthreads();
    for (int o = 512; o; o >>= 1) {
        if (t < o) s[t] += s[t + o];
        __syncthreads();
    }
    if (t == 0) out[0] = s[0] * (1.0f / 1024.0f);
}

// -------------------- 7. write new_queue --------------------
__global__ void k_writeq(const float* __restrict__ Q, float* __restrict__ out) {
    size_t e = (size_t)blockIdx.x * blockDim.x + threadIdx.x;
    int k4 = (int)(e % (KQ / 4));
    int d  = (int)(e / (KQ / 4));
    int k  = k4 * 4;
    float x, y, z, w;
    if (k >= BATCH) {
        float4 qv = *(const float4*)&Q[(size_t)d * KQ + k];
        float4 iv = *(const float4*)&g_inv[k];
        x = qv.x * iv.x; y = qv.y * iv.y; z = qv.z * iv.z; w = qv.w * iv.w;
    } else {
        x = g_zn[(size_t)(k + 0) * DD + d];
        y = g_zn[(size_t)(k + 1) * DD + d];
        z = g_zn[(size_t)(k + 2) * DD + d];
        w = g_zn[(size_t)(k + 3) * DD + d];
    }
    size_t o = (size_t)d * KQ + k;   // out base is d_out+1 (4B aligned) -> scalar stores
    out[o] = x; out[o + 1] = y; out[o + 2] = z; out[o + 3] = w;
}

// -------------------- 8. write new_queue_id + new_ptr --------------------
__global__ void k_writeids(const int* __restrict__ qid, const int* __restrict__ ids,
                           float* __restrict__ out) {
    int k = blockIdx.x * blockDim.x + threadIdx.x;
    if (k < KQ) out[k] = (float)(k < BATCH ? ids[k] : qid[k]);
    if (k == 0) out[KQ] = (float)BATCH;  // (0 + 512) % 131072
}

// -------------------- launch --------------------
extern "C" void kernel_launch(void* const* d_in, const int* in_sizes, int n_in,
                              void* d_out, int out_size) {
    const float* predict0 = (const float*)d_in[0];
    const float* predict1 = (const float*)d_in[1];
    const float* project0 = (const float*)d_in[2];
    const float* project1 = (const float*)d_in[3];
    const float* queue    = (const float*)d_in[4];
    const int*   queue_id = (const int*)d_in[5];
    const int*   ids      = (const int*)d_in[6];
    float* out = (float*)d_out;

    cudaFuncSetAttribute(k_mma, cudaFuncAttributeMaxDynamicSharedMemorySize, SM_DYN);

    k_norm_rows<<<RR, 128>>>(predict0, predict1, project0, project1);
    k_colnorm<<<KQ / 256, 256>>>(queue);
    k_mma<<<NTIL, 256, SM_DYN>>>(queue, queue_id, ids);
    k_argreduce<<<RR, 256>>>();
    k_refine<<<RR, 128>>>(queue, queue_id, ids);
    k_loss<<<RR, 128>>>(queue);
    k_lossred<<<1, 1024>>>(out);
    k_writeq<<<((size_t)DD * KQ / 4) / 256, 256>>>(queue, out + 1);
    k_writeids<<<KQ / 256, 256>>>(queue_id, ids, out + 1 + (size_t)DD * KQ);
}